// round 17
// baseline (speedup 1.0000x reference)
#include <cuda_runtime.h>
#include <cuda_fp16.h>
#include <math.h>
#include <stdint.h>

// Problem dims
#define Bn 8
#define Tn 1024
#define Dn 512
#define Hn 1024
#define En 8
#define Kn 2
#define Nn (Bn * Tn)          // 8192 tokens
#define LOG_2PI 1.8378770664093453f

// ---------------- scratch (static __device__ globals) ----------------------
__device__ __half g_hh[(size_t)Nn * Kn * Hn];          // gelu(h) fp16, [slot][H]
__device__ __half g_xh[(size_t)Nn * Dn];               // x cast to fp16
__device__ float  g_gate[Nn * Kn];
__device__ int    g_counts[En];
__device__ int    g_list[En][Nn];
__device__ int    g_done[En * 64];                     // gemm1 tile completion
__device__ int    g_tdone = 0;                         // table completion (reset by fused_gemm)
__device__ __align__(16) float2 g_tab[Bn * En * Dn];   // (isig2, mu*isig2)
__device__ float  g_C[Bn * En];                        // per-(b,e) constant
__device__ __half g_w1[(size_t)En * Dn * Hn];          // W1 [E][D][H] fp16 (k-major)
__device__ __half g_w2[(size_t)En * Hn * Dn];          // W2 [E][H][D] fp16 (k-major)

// ---------------- helpers ---------------------------------------------------
__device__ __forceinline__ uint32_t smem_u32(const void* p) {
    uint32_t a;
    asm("{ .reg .u64 t; cvta.to.shared.u64 t, %1; cvt.u32.u64 %0, t; }" : "=r"(a) : "l"(p));
    return a;
}
__device__ __forceinline__ void ldsm4(uint32_t* r, uint32_t addr) {
    asm volatile("ldmatrix.sync.aligned.m8n8.x4.shared.b16 {%0,%1,%2,%3}, [%4];"
        : "=r"(r[0]), "=r"(r[1]), "=r"(r[2]), "=r"(r[3]) : "r"(addr));
}
__device__ __forceinline__ void ldsm4t(uint32_t* r, uint32_t addr) {
    asm volatile("ldmatrix.sync.aligned.m8n8.x4.trans.shared.b16 {%0,%1,%2,%3}, [%4];"
        : "=r"(r[0]), "=r"(r[1]), "=r"(r[2]), "=r"(r[3]) : "r"(addr));
}
__device__ __forceinline__ void mma16816(float* c, const uint32_t* a, const uint32_t* b) {
    asm volatile("mma.sync.aligned.m16n8k16.row.col.f32.f16.f16.f32 "
        "{%0,%1,%2,%3}, {%4,%5,%6,%7}, {%8,%9}, {%0,%1,%2,%3};"
        : "+f"(c[0]), "+f"(c[1]), "+f"(c[2]), "+f"(c[3])
        : "r"(a[0]), "r"(a[1]), "r"(a[2]), "r"(a[3]), "r"(b[0]), "r"(b[1]));
}
__device__ __forceinline__ void red2(float* ptr, float v0, float v1) {
    asm volatile("red.global.add.v2.f32 [%0], {%1, %2};"
        :: "l"(ptr), "f"(v0), "f"(v1) : "memory");
}
#define CPA16(dst, src) asm volatile("cp.async.cg.shared.global [%0], [%1], 16;" :: "r"(dst), "l"(src) : "memory")
#define CPC()  asm volatile("cp.async.commit_group;" ::: "memory")
#define CPW0() asm volatile("cp.async.wait_group 0;" ::: "memory")

// ---------------- prep kernel: table + weight-cast + gate (heterogeneous) --
// bids [0,64): per-(b,e) table + constants + counter zeroing -> bump g_tdone
// bids [64,4160): W1+W2 fp32->fp16 cast (independent)
// bids [4160,4672): gating (spins until g_tdone>=64; table bids long retired)
#define NW4 (En * Dn * Hn / 4)
#define CASTB (NW4 / 256)              // 4096
#define PREPB (64 + CASTB + Nn / 16)   // 4672
__global__ __launch_bounds__(256, 3) void prep_kernel(const float* __restrict__ W1,
                                                      const float* __restrict__ W2,
                                                      __half* __restrict__ o1,
                                                      __half* __restrict__ o2,
                                                      const float* __restrict__ log_sigmas,
                                                      const float* __restrict__ mus,
                                                      const float* __restrict__ x,
                                                      __half* __restrict__ xh,
                                                      float* __restrict__ y,
                                                      float* __restrict__ out_lp,
                                                      float* __restrict__ out_ti,
                                                      int has_lp, int has_ti) {
    __shared__ __align__(16) float2 stab[En * Dn];   // 32 KB (gate phase only)
    int tid = threadIdx.x;
    int bid = blockIdx.x;

    if (bid < 64) {
        // ---- table phase ----
        int be = bid;
        if (be == 0 && tid < En) g_counts[tid] = 0;
        if (tid < 8) g_done[be * 8 + tid] = 0;
        float* red = (float*)stab;
        float s = 0.0f;
        for (int d = tid; d < Dn; d += 256) {
            float ls = log_sigmas[be * Dn + d];
            float mu = mus[be * Dn + d];
            float s2 = __expf(-2.0f * ls);
            g_tab[be * Dn + d] = make_float2(s2, mu * s2);
            s += -0.5f * mu * mu * s2 - ls;
        }
        red[tid] = s;
        __syncthreads();
        for (int o = 128; o > 0; o >>= 1) {
            if (tid < o) red[tid] += red[tid + o];
            __syncthreads();
        }
        if (tid == 0) g_C[be] = red[0] - 0.5f * LOG_2PI * (float)Dn;
        __threadfence();
        __syncthreads();
        if (tid == 0) atomicAdd(&g_tdone, 1);
        return;
    }
    if (bid < 64 + CASTB) {
        // ---- weight cast phase ----
        int i = (bid - 64) * 256 + tid;
        float4 a = ((const float4*)W1)[i];
        float4 b = ((const float4*)W2)[i];
        __half2 a0 = __floats2half2_rn(a.x, a.y), a1 = __floats2half2_rn(a.z, a.w);
        __half2 b0 = __floats2half2_rn(b.x, b.y), b1 = __floats2half2_rn(b.z, b.w);
        uint2 pa, pb;
        pa.x = *(uint32_t*)&a0; pa.y = *(uint32_t*)&a1;
        pb.x = *(uint32_t*)&b0; pb.y = *(uint32_t*)&b1;
        ((uint2*)o1)[i] = pa;
        ((uint2*)o2)[i] = pb;
        return;
    }

    // ---- gate phase ----
    int gb = bid - (64 + CASTB);           // 0..511
    int warp = tid >> 5, lane = tid & 31;
    int b = gb >> 6;                       // 64 CTAs per batch

    // zero this CTA's 16-token slice of y
    {
        float4* yz = (float4*)(y + (size_t)gb * 16 * Dn);
        float4 z = make_float4(0.f, 0.f, 0.f, 0.f);
#pragma unroll
        for (int i = 0; i < 8; i++) yz[tid + 256 * i] = z;
    }
    // wait for table (table bids are lowest -> dispatched & retired first)
    if (tid == 0) {
        volatile int* p = &g_tdone;
        while (*p < 64) { __nanosleep(32); }
        __threadfence();
    }
    __syncthreads();
    {
        const float4* src = (const float4*)(g_tab + b * En * Dn);
        float4* dst = (float4*)stab;
        for (int i = tid; i < En * Dn / 2; i += 256) dst[i] = src[i];
    }
    __syncthreads();

    int t0 = gb * 16 + warp * 2;
    int t1 = t0 + 1;

    float xr0[16], xr1[16];
#pragma unroll
    for (int i = 0; i < 8; i++) {
        float2 v0 = *(const float2*)(x + (size_t)t0 * Dn + lane * 2 + 64 * i);
        float2 v1 = *(const float2*)(x + (size_t)t1 * Dn + lane * 2 + 64 * i);
        xr0[2 * i] = v0.x; xr0[2 * i + 1] = v0.y;
        xr1[2 * i] = v1.x; xr1[2 * i + 1] = v1.y;
    }
#pragma unroll
    for (int i = 0; i < 8; i++) {
        __half2 h0 = __floats2half2_rn(xr0[2 * i], xr0[2 * i + 1]);
        __half2 h1 = __floats2half2_rn(xr1[2 * i], xr1[2 * i + 1]);
        *(uint32_t*)(xh + (size_t)t0 * Dn + lane * 2 + 64 * i) = *(uint32_t*)&h0;
        *(uint32_t*)(xh + (size_t)t1 * Dn + lane * 2 + 64 * i) = *(uint32_t*)&h1;
    }

    float s0[En], s1[En];
#pragma unroll
    for (int e = 0; e < En; e++) {
        const float4* tb = (const float4*)(stab + e * Dn);
        float a10 = 0.0f, a20 = 0.0f, a11 = 0.0f, a21 = 0.0f;
#pragma unroll
        for (int i = 0; i < 8; i++) {
            float4 p = tb[lane + 32 * i];
            a10 = fmaf(xr0[2 * i] * p.x, xr0[2 * i], a10);
            a20 = fmaf(xr0[2 * i], p.y, a20);
            a10 = fmaf(xr0[2 * i + 1] * p.z, xr0[2 * i + 1], a10);
            a20 = fmaf(xr0[2 * i + 1], p.w, a20);
            a11 = fmaf(xr1[2 * i] * p.x, xr1[2 * i], a11);
            a21 = fmaf(xr1[2 * i], p.y, a21);
            a11 = fmaf(xr1[2 * i + 1] * p.z, xr1[2 * i + 1], a11);
            a21 = fmaf(xr1[2 * i + 1], p.w, a21);
        }
        s0[e] = a20 - 0.5f * a10;
        s1[e] = a21 - 0.5f * a11;
    }
#pragma unroll
    for (int o = 16; o > 0; o >>= 1) {
#pragma unroll
        for (int e = 0; e < En; e++) {
            s0[e] += __shfl_xor_sync(0xffffffffu, s0[e], o);
            s1[e] += __shfl_xor_sync(0xffffffffu, s1[e], o);
        }
    }

    if (lane < 2) {
        int t = (lane == 0) ? t0 : t1;
        float lp[En];
#pragma unroll
        for (int e = 0; e < En; e++)
            lp[e] = ((lane == 0) ? s0[e] : s1[e]) + g_C[b * En + e];
        int e0 = 0;
#pragma unroll
        for (int e = 1; e < En; e++) if (lp[e] > lp[e0]) e0 = e;
        int e1 = -1;
#pragma unroll
        for (int e = 0; e < En; e++) {
            if (e == e0) continue;
            if (e1 < 0 || lp[e] > lp[e1]) e1 = e;
        }
        float p1 = __expf(lp[e1] - lp[e0]);
        float inv = 1.0f / (1.0f + p1);
        g_gate[t * 2 + 0] = inv;
        g_gate[t * 2 + 1] = p1 * inv;
        int p = atomicAdd(&g_counts[e0], 1);
        g_list[e0][p] = (t << 1) | 0;
        p = atomicAdd(&g_counts[e1], 1);
        g_list[e1][p] = (t << 1) | 1;
        if (has_lp) {
#pragma unroll
            for (int e = 0; e < En; e++) out_lp[t * En + e] = lp[e];
        }
        if (has_ti) {
            out_ti[t * 2 + 0] = (float)e0;
            out_ti[t * 2 + 1] = (float)e1;
        }
    }
}

// ---------------- fused grouped GEMM (gemm1 + dependent gemm2) -------------
#define ROWB_A 144
#define ROWB_B 272
#define STG_A (128 * ROWB_A)           // 18432
#define STG_B (64 * ROWB_B)            // 17408
#define STG_BYTES (STG_A + STG_B)      // 35840
#define NSTG 2
#define G1BLKS 4096                    // 8n * 64y * 8e

template <int MODE>
__device__ __forceinline__ void gemm_body(int n0, int row0, int cnt, int e,
                                          const __half* __restrict__ Aglob,
                                          const __half* __restrict__ Bg,
                                          const float* __restrict__ bias,
                                          float* __restrict__ outf,
                                          __half* __restrict__ outh,
                                          char* sdyn, int* ent, int* rowIdx,
                                          float* gw, int* done) {
    constexpr int Ktot = MODE ? Hn : Dn;
    constexpr int Ntot = MODE ? Dn : Hn;
    constexpr int NCH = Ktot / 64;

    int tid = threadIdx.x, lane = tid & 31, wid = tid >> 5;
    int warp_m = wid & 3, warp_n = wid >> 2;

    if (tid < 128) {
        int en = (row0 + tid < cnt) ? g_list[e][row0 + tid] : -1;
        ent[tid] = en;
        gw[tid] = (en >= 0) ? g_gate[en] : 0.0f;
        int safe = g_list[e][row0];
        int use = (en >= 0) ? en : safe;
        rowIdx[tid] = MODE ? use : (use >> 1);
    }
    if (MODE == 1 && tid == 0) {
        volatile int* p = done;
        while (*p < (Hn / 128)) { __nanosleep(32); }
        __threadfence();
    }
    __syncthreads();

    const __half* Be = Bg + (size_t)e * Ktot * Ntot + n0;
    uint32_t sbase = smem_u32(sdyn);

    int amr = tid >> 3, ac8 = tid & 7;
    const __half* aS[4];
    uint32_t aD[4];
#pragma unroll
    for (int j = 0; j < 4; j++) {
        int m = amr + 32 * j;
        aS[j] = Aglob + (size_t)rowIdx[m] * Ktot + ac8 * 8;
        aD[j] = (uint32_t)(m * ROWB_A + ac8 * 16);
    }
    int brr = tid >> 4, bc8 = tid & 15;
    const __half* bS = Be + (size_t)brr * Ntot + bc8 * 8;
    uint32_t bD = (uint32_t)(STG_A + brr * ROWB_B + bc8 * 16);

    float c[2][8][4];
#pragma unroll
    for (int i = 0; i < 2; i++)
#pragma unroll
        for (int j = 0; j < 8; j++)
#pragma unroll
            for (int q = 0; q < 4; q++) c[i][j][q] = 0.0f;

    uint32_t a_row = (uint32_t)(lane & 15);
    uint32_t a_kh  = (uint32_t)((lane >> 4) << 3);
    uint32_t b_krow = (uint32_t)((lane & 7) + (lane & 8));
    uint32_t b_ncol = (uint32_t)((lane >> 4) << 3);
    uint32_t aOff0 = (uint32_t)(warp_m * 32 + a_row) * ROWB_A + a_kh * 2;
    uint32_t aOff1 = aOff0 + 16 * ROWB_A;
    uint32_t bColB = (uint32_t)(warp_n * 64 + b_ncol) * 2;

    auto prefetch = [&](int k0, int s) {
        uint32_t base = sbase + s * STG_BYTES;
#pragma unroll
        for (int j = 0; j < 4; j++) CPA16(base + aD[j], aS[j] + k0);
        const __half* bp = bS + (size_t)k0 * Ntot;
#pragma unroll
        for (int j = 0; j < 4; j++)
            CPA16(base + bD + (uint32_t)(j * 16 * ROWB_B), bp + (size_t)(j * 16) * Ntot);
    };

    prefetch(0, 0);
    CPC();

    for (int cc = 0; cc < NCH; cc++) {
        int s = cc & 1;
        CPW0();
        __syncthreads();
        if (cc + 1 < NCH) {
            prefetch((cc + 1) * 64, s ^ 1);
            CPC();
        }

        uint32_t baseA = sbase + s * STG_BYTES;
        uint32_t baseB = baseA + STG_A;
#pragma unroll
        for (int kk = 0; kk < 4; kk++) {
            uint32_t ah[2][4];
            ldsm4(ah[0], baseA + aOff0 + kk * 32);
            ldsm4(ah[1], baseA + aOff1 + kk * 32);
            uint32_t bh[8][2];
            uint32_t kb = (uint32_t)(kk * 16 + b_krow) * ROWB_B + bColB;
#pragma unroll
            for (int p = 0; p < 4; p++) {
                uint32_t r4[4];
                ldsm4t(r4, baseB + kb + (uint32_t)(p * 16) * 2);
                bh[2 * p][0] = r4[0]; bh[2 * p][1] = r4[1];
                bh[2 * p + 1][0] = r4[2]; bh[2 * p + 1][1] = r4[3];
            }
#pragma unroll
            for (int mt = 0; mt < 2; mt++)
#pragma unroll
                for (int nt = 0; nt < 8; nt++)
                    mma16816(c[mt][nt], ah[mt], bh[nt]);
        }
    }

    // ---- epilogue ----
#pragma unroll
    for (int mt = 0; mt < 2; mt++) {
#pragma unroll
        for (int nt = 0; nt < 8; nt++) {
            int col = n0 + warp_n * 64 + nt * 8 + (lane & 3) * 2;
#pragma unroll
            for (int half = 0; half < 2; half++) {
                int m = warp_m * 32 + mt * 16 + (lane >> 2) + half * 8;
                int en = ent[m];
                if (en < 0) continue;
                float v0 = c[mt][nt][half * 2 + 0] + bias[e * Ntot + col];
                float v1 = c[mt][nt][half * 2 + 1] + bias[e * Ntot + col + 1];
                if (MODE == 0) {
                    float ga = 0.5f * v0 * (1.0f + erff(v0 * 0.7071067811865476f));
                    float gb = 0.5f * v1 * (1.0f + erff(v1 * 0.7071067811865476f));
                    __half2 h2 = __floats2half2_rn(ga, gb);
                    *(uint32_t*)(outh + (size_t)en * Hn + col) = *(uint32_t*)&h2;
                } else {
                    float g = gw[m];
                    int t = en >> 1;
                    red2(outf + (size_t)t * Dn + col, v0 * g, v1 * g);
                }
            }
        }
    }

    if (MODE == 0) {
        __threadfence();
        __syncthreads();
        if (tid == 0) atomicAdd(done, 1);
    }
}

__global__ __launch_bounds__(256, 2) void fused_gemm(const __half* __restrict__ xh,
                                                     const __half* __restrict__ w1,
                                                     const float* __restrict__ b1,
                                                     __half* __restrict__ hh,
                                                     const __half* __restrict__ w2,
                                                     const float* __restrict__ b2,
                                                     float* __restrict__ y) {
    __shared__ int ent[128];
    __shared__ int rowIdx[128];
    __shared__ float gw[128];
    extern __shared__ char sdyn[];
    int bid = blockIdx.x;
    // reset table-done counter for the next launch/replay (before any early-return)
    if (bid == 0 && threadIdx.x == 0) g_tdone = 0;
    if (bid < G1BLKS) {
        int n = bid & 7, yt = (bid >> 3) & 63, e = bid >> 9;
        int cnt = g_counts[e];
        int row0 = yt * 128;
        if (row0 >= cnt) return;
        gemm_body<0>(n * 128, row0, cnt, e, xh, w1, b1, nullptr, hh,
                     sdyn, ent, rowIdx, gw, &g_done[e * 64 + yt]);
    } else {
        int b2i = bid - G1BLKS;
        int n = b2i & 3, yt = (b2i >> 2) & 63, e = b2i >> 8;
        int cnt = g_counts[e];
        int row0 = yt * 128;
        if (row0 >= cnt) return;
        gemm_body<1>(n * 128, row0, cnt, e, hh, w2, b2, y, nullptr,
                     sdyn, ent, rowIdx, gw, &g_done[e * 64 + yt]);
    }
}

// ---------------- launch ----------------------------------------------------
extern "C" void kernel_launch(void* const* d_in, const int* in_sizes, int n_in,
                              void* d_out, int out_size) {
    const float* x   = (const float*)d_in[0];
    const float* mus = (const float*)d_in[1];
    const float* ls  = (const float*)d_in[2];
    const float* W1  = (const float*)d_in[3];
    const float* b1  = (const float*)d_in[4];
    const float* W2  = (const float*)d_in[5];
    const float* b2  = (const float*)d_in[6];
    float* out = (float*)d_out;

    const int Ny  = Nn * Dn;
    const int Nlp = Nn * En;
    const int Nti = Nn * Kn;
    int has_lp = (out_size >= Ny + Nlp) ? 1 : 0;
    int has_ti = (out_size >= Ny + Nlp + Nti) ? 1 : 0;
    float* out_lp = out + Ny;
    float* out_ti = out + Ny + Nlp;

    cudaFuncSetAttribute(fused_gemm, cudaFuncAttributeMaxDynamicSharedMemorySize, NSTG * STG_BYTES);

    __half *w1, *w2, *hh, *xh;
    cudaGetSymbolAddress((void**)&w1, g_w1);
    cudaGetSymbolAddress((void**)&w2, g_w2);
    cudaGetSymbolAddress((void**)&hh, g_hh);
    cudaGetSymbolAddress((void**)&xh, g_xh);

    prep_kernel<<<PREPB, 256>>>(W1, W2, w1, w2, ls, mus, x, xh, out,
                                out_lp, out_ti, has_lp, has_ti);

    fused_gemm<<<G1BLKS + 2048, 256, NSTG * STG_BYTES>>>(xh, w1, b1, hh, w2, b2, out);

    (void)in_sizes; (void)n_in;
}